// round 16
// baseline (speedup 1.0000x reference)
#include <cuda_runtime.h>

#define HIDDEN   64
#define NTHREADS 128     // one batch element per CTA; thread = (unit j, k-half)

// ---------- packed f32x2 helpers ----------
__device__ __forceinline__ unsigned long long ffma2(unsigned long long a,
                                                    unsigned long long b,
                                                    unsigned long long c) {
    unsigned long long d;
    asm("fma.rn.f32x2 %0, %1, %2, %3;" : "=l"(d) : "l"(a), "l"(b), "l"(c));
    return d;
}
__device__ __forceinline__ unsigned long long fadd2(unsigned long long a,
                                                    unsigned long long b) {
    unsigned long long d;
    asm("add.rn.f32x2 %0, %1, %2;" : "=l"(d) : "l"(a), "l"(b));
    return d;
}
__device__ __forceinline__ unsigned long long pack2(float lo, float hi) {
    unsigned long long r;
    asm("mov.b64 %0, {%1, %2};" : "=l"(r) : "f"(lo), "f"(hi));
    return r;
}
__device__ __forceinline__ float2 unpack2(unsigned long long v) {
    float2 r;
    asm("mov.b64 {%0, %1}, %2;" : "=f"(r.x), "=f"(r.y) : "l"(v));
    return r;
}
__device__ __forceinline__ float tanh_approx(float x) {   // 1 MUFU
    float r; asm("tanh.approx.f32 %0, %1;" : "=f"(r) : "f"(x)); return r;
}

struct XTerms { float azh, arh, ain; };   // x-dependent gate terms, precomputed

// 16 packed FFMA2 over one (pre-halved) gate half-row, 2 chains of depth 8
__device__ __forceinline__ float half_dot(const unsigned long long* wg_,
                                          const unsigned long long* hv) {
    unsigned long long q0 = ffma2(wg_[0], hv[0], 0ull);
    unsigned long long q1 = ffma2(wg_[1], hv[1], 0ull);
    #pragma unroll
    for (int i = 1; i < 8; i++) {
        q0 = ffma2(wg_[2 * i],     hv[2 * i],     q0);
        q1 = ffma2(wg_[2 * i + 1], hv[2 * i + 1], q1);
    }
    float2 sp = unpack2(fadd2(q0, q1));
    return sp.x + sp.y;
}

// one GRU timestep; x-terms arrive precomputed so the LDS issues first.
// Gate order z, r, n (R14 schedule). Only change vs R14: zc/zh precomputed
// right after tauz, so the post-nval chain is a single FMA.
__device__ __forceinline__ void gru_step(const XTerms& xt,
                                         const float* __restrict__ hin,
                                         float* __restrict__ hout,
                                         const unsigned long long (*wreg)[16],
                                         float bhhn_h,
                                         float& h_old,
                                         int half, int j)
{
    // load my k-half of h once (8 LDS.128 broadcast), reuse for 3 gates
    unsigned long long hv[16];
    const ulonglong2* h2 = reinterpret_cast<const ulonglong2*>(hin + half * 32);
    #pragma unroll
    for (int i = 0; i < 8; i++) {
        ulonglong2 v = h2[i];
        hv[2 * i]     = v.x;
        hv[2 * i + 1] = v.y;
    }

    float dz = half_dot(wreg[1], hv);                  // pre-halved rows
    dz += __shfl_xor_sync(0xffffffffu, dz, 16);
    float tauz = tanh_approx(dz + xt.azh);
    float z05  = 0.5f * tauz;                          // off-chain (shfl/MUFU shadow)
    float zh   = fmaf(z05, h_old, 0.5f * h_old);       // z*h_old
    float zc   = 0.5f - z05;                           // 1-z

    float dr = half_dot(wreg[0], hv);
    dr += __shfl_xor_sync(0xffffffffu, dr, 16);
    float taur = tanh_approx(dr + xt.arh);

    float dnh = half_dot(wreg[2], hv);
    dnh += __shfl_xor_sync(0xffffffffu, dnh, 16);
    float dnb  = dnh + bhhn_h;                         // 0.5*(dot_n + b_hh_n)
    float nval = tanh_approx(fmaf(taur, dnb, dnb + xt.ain));

    // post-nval critical path: ONE FMA -> STS
    h_old = fmaf(nval, zc, zh);                        // (1-z)*n + z*h

    if (half == 0) hout[j] = h_old;
}

__global__ void __launch_bounds__(NTHREADS, 2)
gru_scan_kernel(const float* __restrict__ x,
                const float* __restrict__ W_ih,
                const float* __restrict__ W_hh,
                const float* __restrict__ b_ih,
                const float* __restrict__ b_hh,
                const float* __restrict__ W_fc,
                const float* __restrict__ b_fc,
                float* __restrict__ out,
                int Btotal, int T)
{
    __shared__ __align__(16) float h_sh[2][HIDDEN];   // ping-pong by parity
    __shared__ float red_sh[4];

    const int tid  = threadIdx.x;
    const int wg   = tid / 32;                 // warp 0..3
    const int lane = tid % 32;
    const int j    = wg * 16 + (lane & 15);    // hidden unit
    const int half = lane >> 4;                // k-half; partner = lane^16
    const int b    = blockIdx.x;               // one batch per CTA

    // ---- 3 gate half-rows in registers, PRE-SCALED by 0.5 (96 regs) ----
    unsigned long long wreg[3][16];
    #pragma unroll
    for (int g = 0; g < 3; g++) {
        const float4* row = reinterpret_cast<const float4*>(
            W_hh + (g * HIDDEN + j) * HIDDEN + half * 32);
        #pragma unroll
        for (int i = 0; i < 8; i++) {
            float4 v = row[i];
            wreg[g][2 * i]     = pack2(0.5f * v.x, 0.5f * v.y);
            wreg[g][2 * i + 1] = pack2(0.5f * v.z, 0.5f * v.w);
        }
    }

    const float wr_h   = 0.5f * W_ih[j];
    const float br_h   = 0.5f * (b_ih[j] + b_hh[j]);
    const float wz_h   = 0.5f * W_ih[HIDDEN + j];
    const float bz_h   = 0.5f * (b_ih[HIDDEN + j] + b_hh[HIDDEN + j]);
    const float wn     = W_ih[2 * HIDDEN + j];
    const float bihn   = b_ih[2 * HIDDEN + j];
    const float bhhn_h = 0.5f * b_hh[2 * HIDDEN + j];
    const float wfc    = W_fc[j];
    const float bfc    = __ldg(b_fc);

    const float* xb = x + (size_t)b * T;
    float h_old = 0.0f;
    if (half == 0) h_sh[0][j] = 0.0f;

    auto mkterms = [&](float xv) {
        XTerms t;
        t.azh = fmaf(xv, wz_h, bz_h);
        t.arh = fmaf(xv, wr_h, br_h);
        t.ain = fmaf(xv, wn,   bihn);
        return t;
    };

    // prologue: depth-4 x prefetch (two float2 in flight)
    const int Teven = T & ~1;                  // 3000
    float2 xq0 = *reinterpret_cast<const float2*>(xb);
    float2 xq1 = (Teven > 2) ? *reinterpret_cast<const float2*>(xb + 2) : xq0;
    XTerms t0 = mkterms(xq0.x);
    __syncthreads();

    for (int t = 0; t < Teven; t += 2) {
        int tn = t + 4;
        if (tn > Teven - 2) tn = Teven - 2;
        float2 xq2 = *reinterpret_cast<const float2*>(xb + tn);

        // step t  (x-terms for t+1 computed BEFORE the barrier)
        gru_step(t0, h_sh[0], h_sh[1], wreg, bhhn_h, h_old, half, j);
        XTerms t1 = mkterms(xq0.y);
        __syncthreads();

        // step t+1 (x-terms for t+2 computed before the barrier)
        gru_step(t1, h_sh[1], h_sh[0], wreg, bhhn_h, h_old, half, j);
        t0 = mkterms(xq1.x);
        __syncthreads();

        xq0 = xq1; xq1 = xq2;
    }
    if (Teven != T) {   // odd tail (not hit for T=3000)
        XTerms tt = mkterms(__ldg(xb + Teven));
        gru_step(tt, h_sh[0], h_sh[1], wreg, bhhn_h, h_old, half, j);
        __syncthreads();
    }

    // ---- out[b] = h . W_fc + b_fc (h identical in both halves' regs) ----
    float v = (half == 0) ? h_old * wfc : 0.0f;
    #pragma unroll
    for (int o = 16; o > 0; o >>= 1)
        v += __shfl_xor_sync(0xffffffffu, v, o);
    if (lane == 0) red_sh[wg] = v;
    __syncthreads();
    if (tid == 0) {
        out[b] = red_sh[0] + red_sh[1] + red_sh[2] + red_sh[3] + bfc;
    }
}

extern "C" void kernel_launch(void* const* d_in, const int* in_sizes, int n_in,
                              void* d_out, int out_size)
{
    const float* x    = (const float*)d_in[0];
    const float* W_ih = (const float*)d_in[1];
    const float* W_hh = (const float*)d_in[2];
    const float* b_ih = (const float*)d_in[3];
    const float* b_hh = (const float*)d_in[4];
    const float* W_fc = (const float*)d_in[5];
    const float* b_fc = (const float*)d_in[6];

    int B = out_size;                 // 256
    int T = in_sizes[0] / B;          // 3000

    gru_scan_kernel<<<B, NTHREADS>>>(x, W_ih, W_hh, b_ih, b_hh, W_fc, b_fc,
                                     (float*)d_out, B, T);
}

// round 17
// speedup vs baseline: 1.0339x; 1.0339x over previous
#include <cuda_runtime.h>

#define HIDDEN   64
#define NTHREADS 128     // one batch element per CTA; thread = (unit j, k-half)

// ---------- packed f32x2 helpers ----------
__device__ __forceinline__ unsigned long long ffma2(unsigned long long a,
                                                    unsigned long long b,
                                                    unsigned long long c) {
    unsigned long long d;
    asm("fma.rn.f32x2 %0, %1, %2, %3;" : "=l"(d) : "l"(a), "l"(b), "l"(c));
    return d;
}
__device__ __forceinline__ unsigned long long fadd2(unsigned long long a,
                                                    unsigned long long b) {
    unsigned long long d;
    asm("add.rn.f32x2 %0, %1, %2;" : "=l"(d) : "l"(a), "l"(b));
    return d;
}
__device__ __forceinline__ unsigned long long pack2(float lo, float hi) {
    unsigned long long r;
    asm("mov.b64 %0, {%1, %2};" : "=l"(r) : "f"(lo), "f"(hi));
    return r;
}
__device__ __forceinline__ float2 unpack2(unsigned long long v) {
    float2 r;
    asm("mov.b64 {%0, %1}, %2;" : "=f"(r.x), "=f"(r.y) : "l"(v));
    return r;
}
__device__ __forceinline__ float tanh_approx(float x) {   // 1 MUFU
    float r; asm("tanh.approx.f32 %0, %1;" : "=f"(r) : "f"(x)); return r;
}

struct XTerms { float azh, arh, ain; };   // x-dependent gate terms, precomputed

// 16 packed FFMA2 over one (pre-halved) gate half-row, 2 chains of depth 8
__device__ __forceinline__ float half_dot(const unsigned long long* wg_,
                                          const unsigned long long* hv) {
    unsigned long long q0 = ffma2(wg_[0], hv[0], 0ull);
    unsigned long long q1 = ffma2(wg_[1], hv[1], 0ull);
    #pragma unroll
    for (int i = 1; i < 8; i++) {
        q0 = ffma2(wg_[2 * i],     hv[2 * i],     q0);
        q1 = ffma2(wg_[2 * i + 1], hv[2 * i + 1], q1);
    }
    float2 sp = unpack2(fadd2(q0, q1));
    return sp.x + sp.y;
}

// one GRU timestep; x-terms arrive precomputed so the LDS issues first.
// Gate order z, r, n — byte-identical to the R14 optimum.
__device__ __forceinline__ void gru_step(const XTerms& xt,
                                         const float* __restrict__ hin,
                                         float* __restrict__ hout,
                                         const unsigned long long (*wreg)[16],
                                         float bhhn_h,
                                         float& h_old,
                                         int half, int j)
{
    // load my k-half of h once (8 LDS.128 broadcast), reuse for 3 gates
    unsigned long long hv[16];
    const ulonglong2* h2 = reinterpret_cast<const ulonglong2*>(hin + half * 32);
    #pragma unroll
    for (int i = 0; i < 8; i++) {
        ulonglong2 v = h2[i];
        hv[2 * i]     = v.x;
        hv[2 * i + 1] = v.y;
    }

    float dz = half_dot(wreg[1], hv);                  // pre-halved rows
    dz += __shfl_xor_sync(0xffffffffu, dz, 16);
    float tauz = tanh_approx(dz + xt.azh);

    float dr = half_dot(wreg[0], hv);
    dr += __shfl_xor_sync(0xffffffffu, dr, 16);
    float taur = tanh_approx(dr + xt.arh);

    float dnh = half_dot(wreg[2], hv);
    dnh += __shfl_xor_sync(0xffffffffu, dnh, 16);
    float dnb  = dnh + bhhn_h;                         // 0.5*(dot_n + b_hh_n)
    float nval = tanh_approx(fmaf(taur, dnb, dnb + xt.ain));

    // h = n + z*(h-n),  z = 0.5*tauz + 0.5  -> 2 FMAs
    float dd = h_old - nval;
    h_old = fmaf(tauz, 0.5f * dd, fmaf(0.5f, dd, nval));

    if (half == 0) hout[j] = h_old;
}

__global__ void __launch_bounds__(NTHREADS, 2)
gru_scan_kernel(const float* __restrict__ x,
                const float* __restrict__ W_ih,
                const float* __restrict__ W_hh,
                const float* __restrict__ b_ih,
                const float* __restrict__ b_hh,
                const float* __restrict__ W_fc,
                const float* __restrict__ b_fc,
                float* __restrict__ out,
                int Btotal, int T)
{
    __shared__ __align__(16) float h_sh[2][HIDDEN];   // ping-pong by parity
    __shared__ float red_sh[4];

    const int tid  = threadIdx.x;
    const int wg   = tid / 32;                 // warp 0..3
    const int lane = tid % 32;
    const int j    = wg * 16 + (lane & 15);    // hidden unit
    const int half = lane >> 4;                // k-half; partner = lane^16
    const int b    = blockIdx.x;               // one batch per CTA

    // ---- 3 gate half-rows in registers, PRE-SCALED by 0.5 (96 regs) ----
    unsigned long long wreg[3][16];
    #pragma unroll
    for (int g = 0; g < 3; g++) {
        const float4* row = reinterpret_cast<const float4*>(
            W_hh + (g * HIDDEN + j) * HIDDEN + half * 32);
        #pragma unroll
        for (int i = 0; i < 8; i++) {
            float4 v = row[i];
            wreg[g][2 * i]     = pack2(0.5f * v.x, 0.5f * v.y);
            wreg[g][2 * i + 1] = pack2(0.5f * v.z, 0.5f * v.w);
        }
    }

    const float wr_h   = 0.5f * W_ih[j];
    const float br_h   = 0.5f * (b_ih[j] + b_hh[j]);
    const float wz_h   = 0.5f * W_ih[HIDDEN + j];
    const float bz_h   = 0.5f * (b_ih[HIDDEN + j] + b_hh[HIDDEN + j]);
    const float wn     = W_ih[2 * HIDDEN + j];
    const float bihn   = b_ih[2 * HIDDEN + j];
    const float bhhn_h = 0.5f * b_hh[2 * HIDDEN + j];
    const float wfc    = W_fc[j];
    const float bfc    = __ldg(b_fc);

    const float* xb = x + (size_t)b * T;
    float h_old = 0.0f;
    if (half == 0) h_sh[0][j] = 0.0f;

    auto mkterms = [&](float xv) {
        XTerms t;
        t.azh = fmaf(xv, wz_h, bz_h);
        t.arh = fmaf(xv, wr_h, br_h);
        t.ain = fmaf(xv, wn,   bihn);
        return t;
    };

    // main loop: unroll x4 (T=3000 divisible by 4), float4 x loads (16B aligned
    // since T*4B is a multiple of 16), static ping-pong parity, mkterms placed
    // before each barrier exactly as in R14.
    const int T4 = T & ~3;                     // 3000
    float4 xq = *reinterpret_cast<const float4*>(xb);
    XTerms t0 = mkterms(xq.x);
    __syncthreads();

    for (int t = 0; t < T4; t += 4) {
        int tn = t + 4;
        if (tn > T4 - 4) tn = T4 - 4;
        float4 xq_next = *reinterpret_cast<const float4*>(xb + tn);

        gru_step(t0, h_sh[0], h_sh[1], wreg, bhhn_h, h_old, half, j);
        XTerms t1 = mkterms(xq.y);
        __syncthreads();

        gru_step(t1, h_sh[1], h_sh[0], wreg, bhhn_h, h_old, half, j);
        XTerms t2 = mkterms(xq.z);
        __syncthreads();

        gru_step(t2, h_sh[0], h_sh[1], wreg, bhhn_h, h_old, half, j);
        XTerms t3 = mkterms(xq.w);
        __syncthreads();

        gru_step(t3, h_sh[1], h_sh[0], wreg, bhhn_h, h_old, half, j);
        t0 = mkterms(xq_next.x);
        __syncthreads();

        xq = xq_next;
    }
    // tail (0..3 steps; not hit for T=3000)
    {
        float* hb[2] = { h_sh[0], h_sh[1] };
        int p = 0;
        for (int t = T4; t < T; t++) {
            XTerms tt = mkterms(__ldg(xb + t));
            gru_step(tt, hb[p], hb[p ^ 1], wreg, bhhn_h, h_old, half, j);
            __syncthreads();
            p ^= 1;
        }
    }

    // ---- out[b] = h . W_fc + b_fc (h identical in both halves' regs) ----
    float v = (half == 0) ? h_old * wfc : 0.0f;
    #pragma unroll
    for (int o = 16; o > 0; o >>= 1)
        v += __shfl_xor_sync(0xffffffffu, v, o);
    if (lane == 0) red_sh[wg] = v;
    __syncthreads();
    if (tid == 0) {
        out[b] = red_sh[0] + red_sh[1] + red_sh[2] + red_sh[3] + bfc;
    }
}

extern "C" void kernel_launch(void* const* d_in, const int* in_sizes, int n_in,
                              void* d_out, int out_size)
{
    const float* x    = (const float*)d_in[0];
    const float* W_ih = (const float*)d_in[1];
    const float* W_hh = (const float*)d_in[2];
    const float* b_ih = (const float*)d_in[3];
    const float* b_hh = (const float*)d_in[4];
    const float* W_fc = (const float*)d_in[5];
    const float* b_fc = (const float*)d_in[6];

    int B = out_size;                 // 256
    int T = in_sizes[0] / B;          // 3000

    gru_scan_kernel<<<B, NTHREADS>>>(x, W_ih, W_hh, b_ih, b_hh, W_fc, b_fc,
                                     (float*)d_out, B, T);
}